// round 2
// baseline (speedup 1.0000x reference)
#include <cuda_runtime.h>
#include <math.h>

#define N_NODES 50000
#define E_EDGES 800000
#define E_TOT   850000   // E + N self loops
#define IN_DIM  1280
#define HID     256
#define NHEAD   4
#define DHEAD   64

// ---------------- scratch (device globals: no allocation allowed) ----------------
__device__ float g_h[N_NODES * HID];
__device__ float g_xl[N_NODES * HID];
__device__ float g_xr[N_NODES * HID];
__device__ float g_logits[E_TOT * NHEAD];
__device__ float g_m[N_NODES * NHEAD];
__device__ float g_denom[N_NODES * NHEAD];
__device__ float g_agg[N_NODES * HID];

// ---------------- helpers ----------------
__device__ __forceinline__ void atomicMaxF(float* addr, float v) {
    if (v >= 0.f) atomicMax((int*)addr, __float_as_int(v));
    else          atomicMin((unsigned int*)addr, __float_as_uint(v));
}

// ---------------- SGEMM: C[M,N] = A[M,K] @ B[K,N] + bias ----------------
// BM=BN=128, BK=8, 256 threads, 8x8 per thread.
__global__ void __launch_bounds__(256)
sgemm_bias(const float* __restrict__ A, const float* __restrict__ B,
           const float* __restrict__ bias, float* __restrict__ C,
           int M, int N, int K)
{
    __shared__ float As[8][128];
    __shared__ float Bs[8][128];
    const int tid = threadIdx.x;
    const int rowBase = blockIdx.y * 128;
    const int colBase = blockIdx.x * 128;
    const int trow = tid >> 4;          // 0..15
    const int tcol = tid & 15;          // 0..15
    const int aRow = tid >> 1;          // 0..127
    const int aCol = (tid & 1) * 4;     // 0 or 4
    const int bRow = tid >> 5;          // 0..7
    const int bCol = (tid & 31) * 4;    // 0..124

    float acc[8][8];
#pragma unroll
    for (int i = 0; i < 8; i++)
#pragma unroll
        for (int j = 0; j < 8; j++) acc[i][j] = 0.f;

    const bool aValid = (rowBase + aRow) < M;
    const float* Aptr = A + (size_t)(rowBase + aRow) * K + aCol;
    const float* Bptr = B + (size_t)bRow * N + colBase + bCol;

    for (int k0 = 0; k0 < K; k0 += 8) {
        float4 av = aValid ? *(const float4*)(Aptr + k0) : make_float4(0.f, 0.f, 0.f, 0.f);
        float4 bv = *(const float4*)(Bptr + (size_t)k0 * N);
        As[aCol + 0][aRow] = av.x;
        As[aCol + 1][aRow] = av.y;
        As[aCol + 2][aRow] = av.z;
        As[aCol + 3][aRow] = av.w;
        *(float4*)&Bs[bRow][bCol] = bv;
        __syncthreads();
#pragma unroll
        for (int kk = 0; kk < 8; kk++) {
            float ar[8], br[8];
#pragma unroll
            for (int i = 0; i < 8; i++) ar[i] = As[kk][trow * 8 + i];
#pragma unroll
            for (int j = 0; j < 8; j++) br[j] = Bs[kk][tcol * 8 + j];
#pragma unroll
            for (int i = 0; i < 8; i++)
#pragma unroll
                for (int j = 0; j < 8; j++) acc[i][j] += ar[i] * br[j];
        }
        __syncthreads();
    }

    const int c0 = colBase + tcol * 8;
    float4 b0 = *(const float4*)&bias[c0];
    float4 b1 = *(const float4*)&bias[c0 + 4];
#pragma unroll
    for (int i = 0; i < 8; i++) {
        int r = rowBase + trow * 8 + i;
        if (r < M) {
            float4 o0 = make_float4(acc[i][0] + b0.x, acc[i][1] + b0.y,
                                    acc[i][2] + b0.z, acc[i][3] + b0.w);
            float4 o1 = make_float4(acc[i][4] + b1.x, acc[i][5] + b1.y,
                                    acc[i][6] + b1.z, acc[i][7] + b1.w);
            *(float4*)&C[(size_t)r * N + c0]     = o0;
            *(float4*)&C[(size_t)r * N + c0 + 4] = o1;
        }
    }
}

// ---------------- per-layer init ----------------
__global__ void k_init_m()
{
    int i = blockIdx.x * blockDim.x + threadIdx.x;
    if (i < N_NODES * NHEAD) { g_m[i] = -INFINITY; g_denom[i] = 0.f; }
}
__global__ void k_zero_agg()
{
    int i = blockIdx.x * blockDim.x + threadIdx.x;
    if (i < N_NODES * HID) g_agg[i] = 0.f;
}

// ---------------- pass A: logits + segment max (warp per edge) ----------------
__global__ void __launch_bounds__(256)
k_edge_logits(const int* __restrict__ ei, const float* __restrict__ att)
{
    int warp = (blockIdx.x * blockDim.x + threadIdx.x) >> 5;
    if (warp >= E_TOT) return;
    int lane = threadIdx.x & 31;
    int src, dst;
    if (warp < E_EDGES) { src = ei[warp]; dst = ei[E_EDGES + warp]; }
    else                { src = warp - E_EDGES; dst = src; }

    int base = lane * 8;  // lane covers elements [base, base+8): all within head lane>>3
    const float4* pl = (const float4*)(g_xl + (size_t)src * HID + base);
    const float4* pr = (const float4*)(g_xr + (size_t)dst * HID + base);
    const float4* pa = (const float4*)(att + base);
    float4 l0 = pl[0], l1 = pl[1];
    float4 r0 = pr[0], r1 = pr[1];
    float4 a0 = pa[0], a1 = pa[1];

    float s, t;
    t = l0.x + r0.x; s  = (t > 0.f ? t : 0.2f * t) * a0.x;
    t = l0.y + r0.y; s += (t > 0.f ? t : 0.2f * t) * a0.y;
    t = l0.z + r0.z; s += (t > 0.f ? t : 0.2f * t) * a0.z;
    t = l0.w + r0.w; s += (t > 0.f ? t : 0.2f * t) * a0.w;
    t = l1.x + r1.x; s += (t > 0.f ? t : 0.2f * t) * a1.x;
    t = l1.y + r1.y; s += (t > 0.f ? t : 0.2f * t) * a1.y;
    t = l1.z + r1.z; s += (t > 0.f ? t : 0.2f * t) * a1.z;
    t = l1.w + r1.w; s += (t > 0.f ? t : 0.2f * t) * a1.w;

    // reduce within 8-lane head groups
    s += __shfl_xor_sync(0xffffffffu, s, 4);
    s += __shfl_xor_sync(0xffffffffu, s, 2);
    s += __shfl_xor_sync(0xffffffffu, s, 1);

    if ((lane & 7) == 0) {
        int h = lane >> 3;
        g_logits[(size_t)warp * NHEAD + h] = s;
        atomicMaxF(&g_m[dst * NHEAD + h], s);
    }
}

// ---------------- pass B: exp + segment sum (thread per edge-head) ----------------
__global__ void k_edge_exp(const int* __restrict__ ei, float* __restrict__ aOut)
{
    int idx = blockIdx.x * blockDim.x + threadIdx.x;
    if (idx >= E_TOT * NHEAD) return;
    int e = idx >> 2, h = idx & 3;
    int dst = (e < E_EDGES) ? ei[E_EDGES + e] : e - E_EDGES;
    float a = __expf(g_logits[idx] - g_m[dst * NHEAD + h]);
    aOut[idx] = a;                     // unnormalized, normalized in pass C
    atomicAdd(&g_denom[dst * NHEAD + h], a);
}

// ---------------- pass C: normalize alpha + scatter aggregate (warp per edge) ----------------
__global__ void __launch_bounds__(256)
k_edge_agg(const int* __restrict__ ei, float* __restrict__ alpha)
{
    int warp = (blockIdx.x * blockDim.x + threadIdx.x) >> 5;
    if (warp >= E_TOT) return;
    int lane = threadIdx.x & 31;
    int src, dst;
    if (warp < E_EDGES) { src = ei[warp]; dst = ei[E_EDGES + warp]; }
    else                { src = warp - E_EDGES; dst = src; }

    float al = 0.f;
    if (lane < NHEAD) {
        float a = alpha[(size_t)warp * NHEAD + lane];
        al = a / (g_denom[dst * NHEAD + lane] + 1e-16f);
        alpha[(size_t)warp * NHEAD + lane] = al;   // final output alpha
    }
    al = __shfl_sync(0xffffffffu, al, lane >> 3);  // broadcast head's alpha to its 8 lanes

    int base = lane * 8;
    const float4* pl = (const float4*)(g_xl + (size_t)src * HID + base);
    float4 l0 = pl[0], l1 = pl[1];
    float* o = g_agg + (size_t)dst * HID + base;
    atomicAdd(o + 0, l0.x * al);
    atomicAdd(o + 1, l0.y * al);
    atomicAdd(o + 2, l0.z * al);
    atomicAdd(o + 3, l0.w * al);
    atomicAdd(o + 4, l1.x * al);
    atomicAdd(o + 5, l1.y * al);
    atomicAdd(o + 6, l1.z * al);
    atomicAdd(o + 7, l1.w * al);
}

// ---------------- pass D: bias + residual + ELU, writes new h in place ----------------
__global__ void k_node_finish(const float* __restrict__ bias)
{
    int i = blockIdx.x * blockDim.x + threadIdx.x;
    if (i >= N_NODES * HID) return;
    float v = g_agg[i] + bias[i & (HID - 1)] + g_h[i];
    g_h[i] = v > 0.f ? v : expm1f(v);
}

// ---------------- classifier: warp per node ----------------
__global__ void k_clf(const float* __restrict__ W, const float* __restrict__ b,
                      float* __restrict__ preds)
{
    int warp = (blockIdx.x * blockDim.x + threadIdx.x) >> 5;
    if (warp >= N_NODES) return;
    int lane = threadIdx.x & 31;
    float s = 0.f;
#pragma unroll
    for (int k = lane; k < HID; k += 32) s += g_h[(size_t)warp * HID + k] * W[k];
#pragma unroll
    for (int o = 16; o; o >>= 1) s += __shfl_xor_sync(0xffffffffu, s, o);
    if (lane == 0) preds[warp] = s + b[0];
}

// ---------------- driver ----------------
static void run_layer(const float* Wl, const float* bl, const float* Wr, const float* br,
                      const float* att, const float* bias, const int* ei,
                      float* ph, float* pxl, float* pxr, float* alphaOut)
{
    dim3 g(HID / 128, (N_NODES + 127) / 128);
    sgemm_bias<<<g, 256>>>(ph, Wl, bl, pxl, N_NODES, HID, HID);
    sgemm_bias<<<g, 256>>>(ph, Wr, br, pxr, N_NODES, HID, HID);
    k_init_m<<<(N_NODES * NHEAD + 255) / 256, 256>>>();
    k_zero_agg<<<(N_NODES * HID + 255) / 256, 256>>>();
    k_edge_logits<<<(E_TOT + 7) / 8, 256>>>(ei, att);
    k_edge_exp<<<(E_TOT * NHEAD + 255) / 256, 256>>>(ei, alphaOut);
    k_edge_agg<<<(E_TOT + 7) / 8, 256>>>(ei, alphaOut);
    k_node_finish<<<(N_NODES * HID + 255) / 256, 256>>>(bias);
}

extern "C" void kernel_launch(void* const* d_in, const int* in_sizes, int n_in,
                              void* d_out, int out_size)
{
    const float* x     = (const float*)d_in[0];
    const int*   ei    = (const int*)  d_in[1];
    const float* enc_W = (const float*)d_in[2];
    const float* enc_b = (const float*)d_in[3];
    const float* Wl0   = (const float*)d_in[4];
    const float* bl0   = (const float*)d_in[5];
    const float* Wr0   = (const float*)d_in[6];
    const float* br0   = (const float*)d_in[7];
    const float* att0  = (const float*)d_in[8];
    const float* bias0 = (const float*)d_in[9];
    const float* Wl1   = (const float*)d_in[10];
    const float* bl1   = (const float*)d_in[11];
    const float* Wr1   = (const float*)d_in[12];
    const float* br1   = (const float*)d_in[13];
    const float* att1  = (const float*)d_in[14];
    const float* bias1 = (const float*)d_in[15];
    const float* clf_W = (const float*)d_in[16];
    const float* clf_b = (const float*)d_in[17];

    float* out    = (float*)d_out;
    float* preds  = out;                          // [N]
    float* alpha0 = out + N_NODES;                // [E_TOT, NHEAD]
    float* alpha1 = alpha0 + (size_t)E_TOT * NHEAD;

    float *ph, *pxl, *pxr;
    cudaGetSymbolAddress((void**)&ph,  g_h);
    cudaGetSymbolAddress((void**)&pxl, g_xl);
    cudaGetSymbolAddress((void**)&pxr, g_xr);

    // node encoder: h = x @ enc_W + enc_b
    {
        dim3 g(HID / 128, (N_NODES + 127) / 128);
        sgemm_bias<<<g, 256>>>(x, enc_W, enc_b, ph, N_NODES, HID, IN_DIM);
    }

    run_layer(Wl0, bl0, Wr0, br0, att0, bias0, ei, ph, pxl, pxr, alpha0);
    run_layer(Wl1, bl1, Wr1, br1, att1, bias1, ei, ph, pxl, pxr, alpha1);

    k_clf<<<(N_NODES + 7) / 8, 256>>>(clf_W, clf_b, preds);
}

// round 6
// speedup vs baseline: 1.2309x; 1.2309x over previous
#include <cuda_runtime.h>
#include <cuda_bf16.h>
#include <math.h>
#include <stdint.h>

#define N_NODES 50000
#define E_EDGES 800000
#define E_TOT   850000   // E + N self loops
#define IN_DIM  1280
#define HID     256
#define NHEAD   4
#define DHEAD   64

// ---------------- scratch (device globals: no allocation allowed) ----------------
__device__ float g_h[N_NODES * HID];
__device__ float g_xl[N_NODES * HID];
__device__ float g_xr[N_NODES * HID];
__device__ float g_logits[E_TOT * NHEAD];
__device__ float g_m[N_NODES * NHEAD];
__device__ float g_denom[N_NODES * NHEAD];
__device__ float g_agg[N_NODES * HID];

// split weights, transposed to [N_out][3*K] bf16, role triplets per 8-k block:
// roles (B side): block 3b+0 = hi(k block b), 3b+1 = hi, 3b+2 = lo
__device__ __nv_bfloat16 g_encT[HID * IN_DIM * 3];
__device__ __nv_bfloat16 g_WT[4][HID * HID * 3];   // Wl0, Wr0, Wl1, Wr1

// ---------------- PTX helpers (sm_80-era: compile on plain sm_103 target) ----------------
__device__ __forceinline__ uint32_t smem_u32(const void* p) {
    uint32_t a;
    asm("{ .reg .u64 t; cvta.to.shared.u64 t, %1; cvt.u32.u64 %0, t; }" : "=r"(a) : "l"(p));
    return a;
}
__device__ __forceinline__ void ldsm_x4(uint32_t* r, uint32_t addr) {
    asm volatile("ldmatrix.sync.aligned.m8n8.x4.shared.b16 {%0,%1,%2,%3}, [%4];"
                 : "=r"(r[0]), "=r"(r[1]), "=r"(r[2]), "=r"(r[3]) : "r"(addr));
}
__device__ __forceinline__ void mma16816(float* c, const uint32_t* a, const uint32_t* b) {
    asm volatile("mma.sync.aligned.m16n8k16.row.col.f32.bf16.bf16.f32 "
                 "{%0,%1,%2,%3}, {%4,%5,%6,%7}, {%8,%9}, {%0,%1,%2,%3};"
                 : "+f"(c[0]), "+f"(c[1]), "+f"(c[2]), "+f"(c[3])
                 : "r"(a[0]), "r"(a[1]), "r"(a[2]), "r"(a[3]), "r"(b[0]), "r"(b[1]));
}

// ---------------- tensor-core GEMM: C[M,256] = A[M,K](fp32) @ B'[256,3K](bf16)^T + bias ----
// A split on the fly: role triplet (hi, lo, hi) pairs with B (hi, hi, lo):
//   sum = Ahi*Bhi + Alo*Bhi + Ahi*Blo  (fp32-class accuracy, fp32 accumulate)
__global__ void __launch_bounds__(256, 2)
gemm_tc(const float* __restrict__ A, const __nv_bfloat16* __restrict__ B,
        const float* __restrict__ bias, float* __restrict__ C, int M, int K)
{
    const int K2 = 3 * K;
    const int nCh = K2 >> 5;          // chunks of 32 bf16 along K'
    __shared__ __align__(16) char smbuf[32768];  // 2 x (A 8KB + B 8KB)

    const int tid  = threadIdx.x;
    const int lane = tid & 31;
    const int wid  = tid >> 5;
    const int mw   = wid & 1;         // 2 m-warps
    const int nw   = wid >> 1;        // 4 n-warps
    const int rowBase = blockIdx.y * 128;
    const int colBase = blockIdx.x * 128;

    float acc[4][4][4];
#pragma unroll
    for (int i = 0; i < 4; i++)
#pragma unroll
        for (int j = 0; j < 4; j++)
#pragma unroll
            for (int k = 0; k < 4; k++) acc[i][j][k] = 0.f;

    uint4 aCvt[2], bReg[2];

    auto ldA = [&](int ch) {
#pragma unroll
        for (int i = 0; i < 2; i++) {
            int id = i * 256 + tid;
            int m = id >> 2, c = id & 3;
            int kb = ch * 4 + c;           // global 16B-chunk index along K'
            int b3 = kb / 3;               // original 8-float k-block
            int role = kb - 3 * b3;        // 0: hi, 1: lo, 2: hi
            int rg = rowBase + m;
            float4 v0, v1;
            if (rg < M) {
                const float4* p = (const float4*)(A + (size_t)rg * K + (b3 << 3));
                v0 = p[0]; v1 = p[1];
            } else {
                v0 = make_float4(0.f, 0.f, 0.f, 0.f); v1 = v0;
            }
            float f[8] = {v0.x, v0.y, v0.z, v0.w, v1.x, v1.y, v1.z, v1.w};
            uint32_t w[4];
#pragma unroll
            for (int j = 0; j < 4; j++) {
                float x0 = f[2 * j], x1 = f[2 * j + 1];
                __nv_bfloat16 h0 = __float2bfloat16(x0);
                __nv_bfloat16 h1 = __float2bfloat16(x1);
                __nv_bfloat16 e0, e1;
                if (role == 1) {
                    e0 = __float2bfloat16(x0 - __bfloat162float(h0));
                    e1 = __float2bfloat16(x1 - __bfloat162float(h1));
                } else {
                    e0 = h0; e1 = h1;
                }
                uint16_t u0, u1;
                memcpy(&u0, &e0, 2); memcpy(&u1, &e1, 2);
                w[j] = (uint32_t)u0 | ((uint32_t)u1 << 16);
            }
            aCvt[i] = make_uint4(w[0], w[1], w[2], w[3]);
        }
    };
    auto ldB = [&](int ch) {
#pragma unroll
        for (int i = 0; i < 2; i++) {
            int id = i * 256 + tid;
            int n = id >> 2, c = id & 3;
            bReg[i] = *(const uint4*)(B + (size_t)(colBase + n) * K2 + (ch << 5) + (c << 3));
        }
    };
    auto sts = [&](int buf) {
        char* sa = smbuf + buf * 16384;
        char* sb = sa + 8192;
#pragma unroll
        for (int i = 0; i < 2; i++) {
            int id = i * 256 + tid;
            int m = id >> 2, c = id & 3;
            uint32_t off = m * 64 + ((c ^ ((m >> 1) & 3)) << 4);
            *(uint4*)(sa + off) = aCvt[i];
            *(uint4*)(sb + off) = bReg[i];
        }
    };

    ldA(0); ldB(0);
    for (int ch = 0; ch < nCh; ch++) {
        sts(ch & 1);
        __syncthreads();
        if (ch + 1 < nCh) { ldA(ch + 1); ldB(ch + 1); }

        uint32_t sA = smem_u32(smbuf + (ch & 1) * 16384);
        uint32_t sB = sA + 8192;
#pragma unroll
        for (int ks = 0; ks < 2; ks++) {
            uint32_t af[4][4], bf[2][4];
            int g = lane >> 3;
#pragma unroll
            for (int mt = 0; mt < 4; mt++) {
                int r = mw * 64 + mt * 16 + ((g & 1) << 3) + (lane & 7);
                int kb = ks * 2 + (g >> 1);
                ldsm_x4(af[mt], sA + r * 64 + ((kb ^ ((r >> 1) & 3)) << 4));
            }
#pragma unroll
            for (int p = 0; p < 2; p++) {
                int r = nw * 32 + p * 16 + (((g >> 1) & 1) << 3) + (lane & 7);
                int kb = ks * 2 + (g & 1);
                ldsm_x4(bf[p], sB + r * 64 + ((kb ^ ((r >> 1) & 3)) << 4));
            }
#pragma unroll
            for (int mt = 0; mt < 4; mt++)
#pragma unroll
                for (int nt = 0; nt < 4; nt++)
                    mma16816(acc[mt][nt], af[mt], &bf[nt >> 1][(nt & 1) * 2]);
        }
        // no trailing sync needed: next iter writes the OTHER buffer, and its
        // post-STS sync transitively orders reuse of this one.
    }

    // epilogue: c0,c1 = (m = lane/4, n = (lane&3)*2 + {0,1}); c2,c3 = m+8
#pragma unroll
    for (int mt = 0; mt < 4; mt++) {
        int m0 = rowBase + mw * 64 + mt * 16 + (lane >> 2);
#pragma unroll
        for (int half = 0; half < 2; half++) {
            int rg = m0 + half * 8;
            if (rg < M) {
                float* cp = C + (size_t)rg * 256;
#pragma unroll
                for (int nt = 0; nt < 4; nt++) {
                    int n0 = colBase + nw * 32 + nt * 8 + (lane & 3) * 2;
                    float2 o;
                    o.x = acc[mt][nt][half * 2 + 0] + bias[n0];
                    o.y = acc[mt][nt][half * 2 + 1] + bias[n0 + 1];
                    *(float2*)(cp + n0) = o;
                }
            }
        }
    }
}

// ---------------- weight transpose + split: W[K][N] fp32 -> out[N][3K] bf16 ----------------
// B-side roles per 8-k block b: [3b+0]=hi, [3b+1]=hi, [3b+2]=lo
__global__ void k_wsplit(const float* __restrict__ W, int K, int N,
                         __nv_bfloat16* __restrict__ out)
{
    int idx = blockIdx.x * blockDim.x + threadIdx.x;
    if (idx >= N * K) return;
    int n = idx / K, k = idx - n * K;
    float v = W[(size_t)k * N + n];
    __nv_bfloat16 h = __float2bfloat16(v);
    __nv_bfloat16 l = __float2bfloat16(v - __bfloat162float(h));
    int b = k >> 3, p = k & 7;
    size_t base = (size_t)n * 3 * K + (size_t)(3 * b) * 8 + p;
    out[base]      = h;
    out[base + 8]  = h;
    out[base + 16] = l;
}

// ---------------- helpers ----------------
__device__ __forceinline__ void atomicMaxF(float* addr, float v) {
    if (v >= 0.f) atomicMax((int*)addr, __float_as_int(v));
    else          atomicMin((unsigned int*)addr, __float_as_uint(v));
}

// ---------------- per-layer init ----------------
__global__ void k_init_m()
{
    int i = blockIdx.x * blockDim.x + threadIdx.x;
    if (i < N_NODES * NHEAD) { g_m[i] = -INFINITY; g_denom[i] = 0.f; }
}
__global__ void k_zero_agg()
{
    int i = blockIdx.x * blockDim.x + threadIdx.x;
    if (i < N_NODES * HID) g_agg[i] = 0.f;
}

// ---------------- pass A: logits + segment max (warp per edge) ----------------
__global__ void __launch_bounds__(256)
k_edge_logits(const int* __restrict__ ei, const float* __restrict__ att)
{
    int warp = (blockIdx.x * blockDim.x + threadIdx.x) >> 5;
    if (warp >= E_TOT) return;
    int lane = threadIdx.x & 31;
    int src, dst;
    if (warp < E_EDGES) { src = ei[warp]; dst = ei[E_EDGES + warp]; }
    else                { src = warp - E_EDGES; dst = src; }

    int base = lane * 8;
    const float4* pl = (const float4*)(g_xl + (size_t)src * HID + base);
    const float4* pr = (const float4*)(g_xr + (size_t)dst * HID + base);
    const float4* pa = (const float4*)(att + base);
    float4 l0 = pl[0], l1 = pl[1];
    float4 r0 = pr[0], r1 = pr[1];
    float4 a0 = pa[0], a1 = pa[1];

    float s, t;
    t = l0.x + r0.x; s  = (t > 0.f ? t : 0.2f * t) * a0.x;
    t = l0.y + r0.y; s += (t > 0.f ? t : 0.2f * t) * a0.y;
    t = l0.z + r0.z; s += (t > 0.f ? t : 0.2f * t) * a0.z;
    t = l0.w + r0.w; s += (t > 0.f ? t : 0.2f * t) * a0.w;
    t = l1.x + r1.x; s += (t > 0.f ? t : 0.2f * t) * a1.x;
    t = l1.y + r1.y; s += (t > 0.f ? t : 0.2f * t) * a1.y;
    t = l1.z + r1.z; s += (t > 0.f ? t : 0.2f * t) * a1.z;
    t = l1.w + r1.w; s += (t > 0.f ? t : 0.2f * t) * a1.w;

    s += __shfl_xor_sync(0xffffffffu, s, 4);
    s += __shfl_xor_sync(0xffffffffu, s, 2);
    s += __shfl_xor_sync(0xffffffffu, s, 1);

    if ((lane & 7) == 0) {
        int h = lane >> 3;
        g_logits[(size_t)warp * NHEAD + h] = s;
        atomicMaxF(&g_m[dst * NHEAD + h], s);
    }
}

// ---------------- pass B: exp + segment sum ----------------
__global__ void k_edge_exp(const int* __restrict__ ei, float* __restrict__ aOut)
{
    int idx = blockIdx.x * blockDim.x + threadIdx.x;
    if (idx >= E_TOT * NHEAD) return;
    int e = idx >> 2, h = idx & 3;
    int dst = (e < E_EDGES) ? ei[E_EDGES + e] : e - E_EDGES;
    float a = __expf(g_logits[idx] - g_m[dst * NHEAD + h]);
    aOut[idx] = a;
    atomicAdd(&g_denom[dst * NHEAD + h], a);
}

// ---------------- pass C: normalize alpha + scatter aggregate ----------------
__global__ void __launch_bounds__(256)
k_edge_agg(const int* __restrict__ ei, float* __restrict__ alpha)
{
    int warp = (blockIdx.x * blockDim.x + threadIdx.x) >> 5;
    if (warp >= E_TOT) return;
    int lane = threadIdx.x & 31;
    int src, dst;
    if (warp < E_EDGES) { src = ei[warp]; dst = ei[E_EDGES + warp]; }
    else                { src = warp - E_EDGES; dst = src; }

    float al = 0.f;
    if (lane < NHEAD) {
        float a = alpha[(size_t)warp * NHEAD + lane];
        al = a / (g_denom[dst * NHEAD + lane] + 1e-16f);
        alpha[(size_t)warp * NHEAD + lane] = al;
    }
    al = __shfl_sync(0xffffffffu, al, lane >> 3);

    int base = lane * 8;
    const float4* pl = (const float4*)(g_xl + (size_t)src * HID + base);
    float4 l0 = pl[0], l1 = pl[1];
    float* o = g_agg + (size_t)dst * HID + base;
    atomicAdd(o + 0, l0.x * al);
    atomicAdd(o + 1, l0.y * al);
    atomicAdd(o + 2, l0.z * al);
    atomicAdd(o + 3, l0.w * al);
    atomicAdd(o + 4, l1.x * al);
    atomicAdd(o + 5, l1.y * al);
    atomicAdd(o + 6, l1.z * al);
    atomicAdd(o + 7, l1.w * al);
}

// ---------------- pass D: bias + residual + ELU ----------------
__global__ void k_node_finish(const float* __restrict__ bias)
{
    int i = blockIdx.x * blockDim.x + threadIdx.x;
    if (i >= N_NODES * HID) return;
    float v = g_agg[i] + bias[i & (HID - 1)] + g_h[i];
    g_h[i] = v > 0.f ? v : expm1f(v);
}

// ---------------- classifier ----------------
__global__ void k_clf(const float* __restrict__ W, const float* __restrict__ b,
                      float* __restrict__ preds)
{
    int warp = (blockIdx.x * blockDim.x + threadIdx.x) >> 5;
    if (warp >= N_NODES) return;
    int lane = threadIdx.x & 31;
    float s = 0.f;
#pragma unroll
    for (int k = lane; k < HID; k += 32) s += g_h[(size_t)warp * HID + k] * W[k];
#pragma unroll
    for (int o = 16; o; o >>= 1) s += __shfl_xor_sync(0xffffffffu, s, o);
    if (lane == 0) preds[warp] = s + b[0];
}

// ---------------- driver ----------------
extern "C" void kernel_launch(void* const* d_in, const int* in_sizes, int n_in,
                              void* d_out, int out_size)
{
    const float* x     = (const float*)d_in[0];
    const int*   ei    = (const int*)  d_in[1];
    const float* enc_W = (const float*)d_in[2];
    const float* enc_b = (const float*)d_in[3];
    const float* Wl0   = (const float*)d_in[4];
    const float* bl0   = (const float*)d_in[5];
    const float* Wr0   = (const float*)d_in[6];
    const float* br0   = (const float*)d_in[7];
    const float* att0  = (const float*)d_in[8];
    const float* bias0 = (const float*)d_in[9];
    const float* Wl1   = (const float*)d_in[10];
    const float* bl1   = (const float*)d_in[11];
    const float* Wr1   = (const float*)d_in[12];
    const float* br1   = (const float*)d_in[13];
    const float* att1  = (const float*)d_in[14];
    const float* bias1 = (const float*)d_in[15];
    const float* clf_W = (const float*)d_in[16];
    const float* clf_b = (const float*)d_in[17];

    float* out    = (float*)d_out;
    float* preds  = out;
    float* alpha0 = out + N_NODES;
    float* alpha1 = alpha0 + (size_t)E_TOT * NHEAD;

    float *ph, *pxl, *pxr;
    cudaGetSymbolAddress((void**)&ph,  g_h);
    cudaGetSymbolAddress((void**)&pxl, g_xl);
    cudaGetSymbolAddress((void**)&pxr, g_xr);
    __nv_bfloat16 *encT, *WT;
    cudaGetSymbolAddress((void**)&encT, g_encT);
    cudaGetSymbolAddress((void**)&WT,   g_WT);

    const int WSTRIDE = HID * HID * 3;
    const dim3 GG(2, (N_NODES + 127) / 128);   // 2 x 391

    // prep: transpose + split weights into role-triplet layout
    k_wsplit<<<(HID * IN_DIM + 255) / 256, 256>>>(enc_W, IN_DIM, HID, encT);
    k_wsplit<<<(HID * HID + 255) / 256, 256>>>(Wl0, HID, HID, WT + 0 * WSTRIDE);
    k_wsplit<<<(HID * HID + 255) / 256, 256>>>(Wr0, HID, HID, WT + 1 * WSTRIDE);
    k_wsplit<<<(HID * HID + 255) / 256, 256>>>(Wl1, HID, HID, WT + 2 * WSTRIDE);
    k_wsplit<<<(HID * HID + 255) / 256, 256>>>(Wr1, HID, HID, WT + 3 * WSTRIDE);

    // encoder: h = x @ enc_W + enc_b
    gemm_tc<<<GG, 256>>>(x, encT, enc_b, ph, N_NODES, IN_DIM);

    for (int layer = 0; layer < 2; layer++) {
        const __nv_bfloat16* wl = WT + (layer * 2 + 0) * WSTRIDE;
        const __nv_bfloat16* wr = WT + (layer * 2 + 1) * WSTRIDE;
        const float* bl   = layer ? bl1 : bl0;
        const float* br   = layer ? br1 : br0;
        const float* att  = layer ? att1 : att0;
        const float* bias = layer ? bias1 : bias0;
        float* alphaOut   = layer ? alpha1 : alpha0;

        gemm_tc<<<GG, 256>>>(ph, wl, bl, pxl, N_NODES, HID);
        gemm_tc<<<GG, 256>>>(ph, wr, br, pxr, N_NODES, HID);
        k_init_m<<<(N_NODES * NHEAD + 255) / 256, 256>>>();
        k_zero_agg<<<(N_NODES * HID + 255) / 256, 256>>>();
        k_edge_logits<<<(E_TOT + 7) / 8, 256>>>(ei, att);
        k_edge_exp<<<(E_TOT * NHEAD + 255) / 256, 256>>>(ei, alphaOut);
        k_edge_agg<<<(E_TOT + 7) / 8, 256>>>(ei, alphaOut);
        k_node_finish<<<(N_NODES * HID + 255) / 256, 256>>>(bias);
    }

    k_clf<<<(N_NODES + 7) / 8, 256>>>(clf_W, clf_b, preds);
}

// round 7
// speedup vs baseline: 2.7665x; 2.2475x over previous
#include <cuda_runtime.h>
#include <cuda_bf16.h>
#include <math.h>
#include <stdint.h>
#include <string.h>

#define N_NODES 50000
#define E_EDGES 800000
#define E_TOT   850000   // E + N self loops
#define IN_DIM  1280
#define HID     256
#define NHEAD   4
#define DHEAD   64

// ---------------- scratch (device globals: no allocation allowed) ----------------
__device__ float g_h[N_NODES * HID];
__device__ float g_xl[N_NODES * HID];
__device__ float g_xr[N_NODES * HID];
__device__ float g_logits[E_TOT * NHEAD];

// CSR (in-edges per destination node), built once per launch
__device__ int g_cnt[N_NODES];
__device__ int g_off[N_NODES + 1];
__device__ int g_cur[N_NODES];
__device__ int g_eid[E_TOT];
__device__ int g_srcs[E_TOT];

// split weights, transposed to [N_out][3*K] bf16, role triplets per 8-k block:
// roles (B side): block 3b+0 = hi(k block b), 3b+1 = hi, 3b+2 = lo
__device__ __nv_bfloat16 g_encT[HID * IN_DIM * 3];
__device__ __nv_bfloat16 g_WT[4][HID * HID * 3];   // Wl0, Wr0, Wl1, Wr1

// ---------------- PTX helpers (sm_80-era: compile on plain sm_103 target) ----------------
__device__ __forceinline__ uint32_t smem_u32(const void* p) {
    uint32_t a;
    asm("{ .reg .u64 t; cvta.to.shared.u64 t, %1; cvt.u32.u64 %0, t; }" : "=r"(a) : "l"(p));
    return a;
}
__device__ __forceinline__ void ldsm_x4(uint32_t* r, uint32_t addr) {
    asm volatile("ldmatrix.sync.aligned.m8n8.x4.shared.b16 {%0,%1,%2,%3}, [%4];"
                 : "=r"(r[0]), "=r"(r[1]), "=r"(r[2]), "=r"(r[3]) : "r"(addr));
}
__device__ __forceinline__ void mma16816(float* c, const uint32_t* a, const uint32_t* b) {
    asm volatile("mma.sync.aligned.m16n8k16.row.col.f32.bf16.bf16.f32 "
                 "{%0,%1,%2,%3}, {%4,%5,%6,%7}, {%8,%9}, {%0,%1,%2,%3};"
                 : "+f"(c[0]), "+f"(c[1]), "+f"(c[2]), "+f"(c[3])
                 : "r"(a[0]), "r"(a[1]), "r"(a[2]), "r"(a[3]), "r"(b[0]), "r"(b[1]));
}

// ---------------- tensor-core GEMM: C[M,256] = A[M,K](fp32) @ B'[256,3K](bf16)^T + bias ----
__global__ void __launch_bounds__(256, 2)
gemm_tc(const float* __restrict__ A, const __nv_bfloat16* __restrict__ B,
        const float* __restrict__ bias, float* __restrict__ C, int M, int K)
{
    const int K2 = 3 * K;
    const int nCh = K2 >> 5;
    __shared__ __align__(16) char smbuf[32768];

    const int tid  = threadIdx.x;
    const int lane = tid & 31;
    const int wid  = tid >> 5;
    const int mw   = wid & 1;
    const int nw   = wid >> 1;
    const int rowBase = blockIdx.y * 128;
    const int colBase = blockIdx.x * 128;

    float acc[4][4][4];
#pragma unroll
    for (int i = 0; i < 4; i++)
#pragma unroll
        for (int j = 0; j < 4; j++)
#pragma unroll
            for (int k = 0; k < 4; k++) acc[i][j][k] = 0.f;

    uint4 aCvt[2], bReg[2];

    auto ldA = [&](int ch) {
#pragma unroll
        for (int i = 0; i < 2; i++) {
            int id = i * 256 + tid;
            int m = id >> 2, c = id & 3;
            int kb = ch * 4 + c;
            int b3 = kb / 3;
            int role = kb - 3 * b3;
            int rg = rowBase + m;
            float4 v0, v1;
            if (rg < M) {
                const float4* p = (const float4*)(A + (size_t)rg * K + (b3 << 3));
                v0 = p[0]; v1 = p[1];
            } else {
                v0 = make_float4(0.f, 0.f, 0.f, 0.f); v1 = v0;
            }
            float f[8] = {v0.x, v0.y, v0.z, v0.w, v1.x, v1.y, v1.z, v1.w};
            uint32_t w[4];
#pragma unroll
            for (int j = 0; j < 4; j++) {
                float x0 = f[2 * j], x1 = f[2 * j + 1];
                __nv_bfloat16 h0 = __float2bfloat16(x0);
                __nv_bfloat16 h1 = __float2bfloat16(x1);
                __nv_bfloat16 e0, e1;
                if (role == 1) {
                    e0 = __float2bfloat16(x0 - __bfloat162float(h0));
                    e1 = __float2bfloat16(x1 - __bfloat162float(h1));
                } else {
                    e0 = h0; e1 = h1;
                }
                uint16_t u0, u1;
                memcpy(&u0, &e0, 2); memcpy(&u1, &e1, 2);
                w[j] = (uint32_t)u0 | ((uint32_t)u1 << 16);
            }
            aCvt[i] = make_uint4(w[0], w[1], w[2], w[3]);
        }
    };
    auto ldB = [&](int ch) {
#pragma unroll
        for (int i = 0; i < 2; i++) {
            int id = i * 256 + tid;
            int n = id >> 2, c = id & 3;
            bReg[i] = *(const uint4*)(B + (size_t)(colBase + n) * K2 + (ch << 5) + (c << 3));
        }
    };
    auto sts = [&](int buf) {
        char* sa = smbuf + buf * 16384;
        char* sb = sa + 8192;
#pragma unroll
        for (int i = 0; i < 2; i++) {
            int id = i * 256 + tid;
            int m = id >> 2, c = id & 3;
            uint32_t off = m * 64 + ((c ^ ((m >> 1) & 3)) << 4);
            *(uint4*)(sa + off) = aCvt[i];
            *(uint4*)(sb + off) = bReg[i];
        }
    };

    ldA(0); ldB(0);
    for (int ch = 0; ch < nCh; ch++) {
        sts(ch & 1);
        __syncthreads();
        if (ch + 1 < nCh) { ldA(ch + 1); ldB(ch + 1); }

        uint32_t sA = smem_u32(smbuf + (ch & 1) * 16384);
        uint32_t sB = sA + 8192;
#pragma unroll
        for (int ks = 0; ks < 2; ks++) {
            uint32_t af[4][4], bf[2][4];
            int g = lane >> 3;
#pragma unroll
            for (int mt = 0; mt < 4; mt++) {
                int r = mw * 64 + mt * 16 + ((g & 1) << 3) + (lane & 7);
                int kb = ks * 2 + (g >> 1);
                ldsm_x4(af[mt], sA + r * 64 + ((kb ^ ((r >> 1) & 3)) << 4));
            }
#pragma unroll
            for (int p = 0; p < 2; p++) {
                int r = nw * 32 + p * 16 + (((g >> 1) & 1) << 3) + (lane & 7);
                int kb = ks * 2 + (g & 1);
                ldsm_x4(bf[p], sB + r * 64 + ((kb ^ ((r >> 1) & 3)) << 4));
            }
#pragma unroll
            for (int mt = 0; mt < 4; mt++)
#pragma unroll
                for (int nt = 0; nt < 4; nt++)
                    mma16816(acc[mt][nt], af[mt], &bf[nt >> 1][(nt & 1) * 2]);
        }
    }

#pragma unroll
    for (int mt = 0; mt < 4; mt++) {
        int m0 = rowBase + mw * 64 + mt * 16 + (lane >> 2);
#pragma unroll
        for (int half = 0; half < 2; half++) {
            int rg = m0 + half * 8;
            if (rg < M) {
                float* cp = C + (size_t)rg * 256;
#pragma unroll
                for (int nt = 0; nt < 4; nt++) {
                    int n0 = colBase + nw * 32 + nt * 8 + (lane & 3) * 2;
                    float2 o;
                    o.x = acc[mt][nt][half * 2 + 0] + bias[n0];
                    o.y = acc[mt][nt][half * 2 + 1] + bias[n0 + 1];
                    *(float2*)(cp + n0) = o;
                }
            }
        }
    }
}

// ---------------- weight transpose + split ----------------
__global__ void k_wsplit(const float* __restrict__ W, int K, int N,
                         __nv_bfloat16* __restrict__ out)
{
    int idx = blockIdx.x * blockDim.x + threadIdx.x;
    if (idx >= N * K) return;
    int n = idx / K, k = idx - n * K;
    float v = W[(size_t)k * N + n];
    __nv_bfloat16 h = __float2bfloat16(v);
    __nv_bfloat16 l = __float2bfloat16(v - __bfloat162float(h));
    int b = k >> 3, p = k & 7;
    size_t base = (size_t)n * 3 * K + (size_t)(3 * b) * 8 + p;
    out[base]      = h;
    out[base + 8]  = h;
    out[base + 16] = l;
}

// ---------------- CSR build (once per launch) ----------------
__global__ void k_csr_zero()
{
    int i = blockIdx.x * blockDim.x + threadIdx.x;
    if (i < N_NODES) g_cnt[i] = 0;
}
__global__ void k_csr_count(const int* __restrict__ ei)
{
    int e = blockIdx.x * blockDim.x + threadIdx.x;
    if (e >= E_TOT) return;
    int dst = (e < E_EDGES) ? ei[E_EDGES + e] : e - E_EDGES;
    atomicAdd(&g_cnt[dst], 1);
}
// single-block exclusive scan of g_cnt -> g_off/g_cur
__global__ void __launch_bounds__(1024) k_csr_scan()
{
    __shared__ int sh[1024];
    int tid = threadIdx.x;
    int carry = 0;
    for (int base = 0; base < N_NODES; base += 1024) {
        int i = base + tid;
        int v = (i < N_NODES) ? g_cnt[i] : 0;
        int x = v;
#pragma unroll
        for (int o = 1; o < 1024; o <<= 1) {
            sh[tid] = x; __syncthreads();
            if (tid >= o) x += sh[tid - o];
            __syncthreads();
        }
        if (i < N_NODES) { g_off[i] = carry + x - v; g_cur[i] = carry + x - v; }
        sh[tid] = x; __syncthreads();
        carry += sh[1023];
        __syncthreads();
    }
    if (tid == 0) g_off[N_NODES] = carry;
}
__global__ void k_csr_fill(const int* __restrict__ ei)
{
    int e = blockIdx.x * blockDim.x + threadIdx.x;
    if (e >= E_TOT) return;
    int src, dst;
    if (e < E_EDGES) { src = ei[e]; dst = ei[E_EDGES + e]; }
    else             { src = e - E_EDGES; dst = src; }
    int pos = atomicAdd(&g_cur[dst], 1);
    g_eid[pos]  = e;
    g_srcs[pos] = src;
}

// ---------------- pass A: logits (warp per edge, no atomics) ----------------
__global__ void __launch_bounds__(256)
k_edge_logits(const int* __restrict__ ei, const float* __restrict__ att)
{
    int warp = (blockIdx.x * blockDim.x + threadIdx.x) >> 5;
    if (warp >= E_TOT) return;
    int lane = threadIdx.x & 31;
    int src, dst;
    if (warp < E_EDGES) { src = ei[warp]; dst = ei[E_EDGES + warp]; }
    else                { src = warp - E_EDGES; dst = src; }

    int base = lane * 8;
    const float4* pl = (const float4*)(g_xl + (size_t)src * HID + base);
    const float4* pr = (const float4*)(g_xr + (size_t)dst * HID + base);
    const float4* pa = (const float4*)(att + base);
    float4 l0 = pl[0], l1 = pl[1];
    float4 r0 = pr[0], r1 = pr[1];
    float4 a0 = pa[0], a1 = pa[1];

    float s, t;
    t = l0.x + r0.x; s  = (t > 0.f ? t : 0.2f * t) * a0.x;
    t = l0.y + r0.y; s += (t > 0.f ? t : 0.2f * t) * a0.y;
    t = l0.z + r0.z; s += (t > 0.f ? t : 0.2f * t) * a0.z;
    t = l0.w + r0.w; s += (t > 0.f ? t : 0.2f * t) * a0.w;
    t = l1.x + r1.x; s += (t > 0.f ? t : 0.2f * t) * a1.x;
    t = l1.y + r1.y; s += (t > 0.f ? t : 0.2f * t) * a1.y;
    t = l1.z + r1.z; s += (t > 0.f ? t : 0.2f * t) * a1.z;
    t = l1.w + r1.w; s += (t > 0.f ? t : 0.2f * t) * a1.w;

    s += __shfl_xor_sync(0xffffffffu, s, 4);
    s += __shfl_xor_sync(0xffffffffu, s, 2);
    s += __shfl_xor_sync(0xffffffffu, s, 1);

    if ((lane & 7) == 0) g_logits[(size_t)warp * NHEAD + (lane >> 3)] = s;
}

// ---------------- pass B: node-centric softmax (warp per node) ----------------
#define SCAP 128
__global__ void __launch_bounds__(256)
k_node_soft(float* __restrict__ alphaOut)
{
    __shared__ float4 sa[8][SCAP];
    int warp = (blockIdx.x * blockDim.x + threadIdx.x) >> 5;
    if (warp >= N_NODES) return;
    int lane = threadIdx.x & 31;
    int w = (threadIdx.x >> 5);
    int beg = g_off[warp];
    int deg = g_off[warp + 1] - beg;
    const float4* lg4 = (const float4*)g_logits;
    float4* al4 = (float4*)alphaOut;

    if (deg <= SCAP) {
        for (int i = lane; i < deg; i += 32) sa[w][i] = lg4[g_eid[beg + i]];
        __syncwarp();
        float4 mx = make_float4(-INFINITY, -INFINITY, -INFINITY, -INFINITY);
        for (int i = lane; i < deg; i += 32) {
            float4 v = sa[w][i];
            mx.x = fmaxf(mx.x, v.x); mx.y = fmaxf(mx.y, v.y);
            mx.z = fmaxf(mx.z, v.z); mx.w = fmaxf(mx.w, v.w);
        }
#pragma unroll
        for (int o = 16; o; o >>= 1) {
            mx.x = fmaxf(mx.x, __shfl_xor_sync(0xffffffffu, mx.x, o));
            mx.y = fmaxf(mx.y, __shfl_xor_sync(0xffffffffu, mx.y, o));
            mx.z = fmaxf(mx.z, __shfl_xor_sync(0xffffffffu, mx.z, o));
            mx.w = fmaxf(mx.w, __shfl_xor_sync(0xffffffffu, mx.w, o));
        }
        float4 sm = make_float4(0.f, 0.f, 0.f, 0.f);
        for (int i = lane; i < deg; i += 32) {
            float4 v = sa[w][i];
            v.x = __expf(v.x - mx.x); v.y = __expf(v.y - mx.y);
            v.z = __expf(v.z - mx.z); v.w = __expf(v.w - mx.w);
            sa[w][i] = v;
            sm.x += v.x; sm.y += v.y; sm.z += v.z; sm.w += v.w;
        }
#pragma unroll
        for (int o = 16; o; o >>= 1) {
            sm.x += __shfl_xor_sync(0xffffffffu, sm.x, o);
            sm.y += __shfl_xor_sync(0xffffffffu, sm.y, o);
            sm.z += __shfl_xor_sync(0xffffffffu, sm.z, o);
            sm.w += __shfl_xor_sync(0xffffffffu, sm.w, o);
        }
        float4 inv = make_float4(1.f / (sm.x + 1e-16f), 1.f / (sm.y + 1e-16f),
                                 1.f / (sm.z + 1e-16f), 1.f / (sm.w + 1e-16f));
        __syncwarp();
        for (int i = lane; i < deg; i += 32) {
            float4 v = sa[w][i];
            v.x *= inv.x; v.y *= inv.y; v.z *= inv.z; v.w *= inv.w;
            al4[g_eid[beg + i]] = v;
        }
    } else {
        // fallback (deg > 128): 3 global passes
        float4 mx = make_float4(-INFINITY, -INFINITY, -INFINITY, -INFINITY);
        for (int i = lane; i < deg; i += 32) {
            float4 v = lg4[g_eid[beg + i]];
            mx.x = fmaxf(mx.x, v.x); mx.y = fmaxf(mx.y, v.y);
            mx.z = fmaxf(mx.z, v.z); mx.w = fmaxf(mx.w, v.w);
        }
#pragma unroll
        for (int o = 16; o; o >>= 1) {
            mx.x = fmaxf(mx.x, __shfl_xor_sync(0xffffffffu, mx.x, o));
            mx.y = fmaxf(mx.y, __shfl_xor_sync(0xffffffffu, mx.y, o));
            mx.z = fmaxf(mx.z, __shfl_xor_sync(0xffffffffu, mx.z, o));
            mx.w = fmaxf(mx.w, __shfl_xor_sync(0xffffffffu, mx.w, o));
        }
        float4 sm = make_float4(0.f, 0.f, 0.f, 0.f);
        for (int i = lane; i < deg; i += 32) {
            float4 v = lg4[g_eid[beg + i]];
            sm.x += __expf(v.x - mx.x); sm.y += __expf(v.y - mx.y);
            sm.z += __expf(v.z - mx.z); sm.w += __expf(v.w - mx.w);
        }
#pragma unroll
        for (int o = 16; o; o >>= 1) {
            sm.x += __shfl_xor_sync(0xffffffffu, sm.x, o);
            sm.y += __shfl_xor_sync(0xffffffffu, sm.y, o);
            sm.z += __shfl_xor_sync(0xffffffffu, sm.z, o);
            sm.w += __shfl_xor_sync(0xffffffffu, sm.w, o);
        }
        float4 inv = make_float4(1.f / (sm.x + 1e-16f), 1.f / (sm.y + 1e-16f),
                                 1.f / (sm.z + 1e-16f), 1.f / (sm.w + 1e-16f));
        for (int i = lane; i < deg; i += 32) {
            int e = g_eid[beg + i];
            float4 v = lg4[e];
            v.x = __expf(v.x - mx.x) * inv.x; v.y = __expf(v.y - mx.y) * inv.y;
            v.z = __expf(v.z - mx.z) * inv.z; v.w = __expf(v.w - mx.w) * inv.w;
            al4[e] = v;
        }
    }
}

// ---------------- pass C: node-centric aggregation + bias + residual + ELU ------------
// LAST=0: writes new h into g_h. LAST=1: instead computes preds = elu_out @ clf_W + b.
template <int LAST>
__global__ void __launch_bounds__(256)
k_node_agg(const float* __restrict__ alpha, const float* __restrict__ bias,
           const float* __restrict__ clfW, const float* __restrict__ clfb,
           float* __restrict__ preds)
{
    int warp = (blockIdx.x * blockDim.x + threadIdx.x) >> 5;
    if (warp >= N_NODES) return;
    int lane = threadIdx.x & 31;
    int head = lane >> 3;
    int beg = g_off[warp];
    int deg = g_off[warp + 1] - beg;
    const float4* al4 = (const float4*)alpha;

    float acc[8];
#pragma unroll
    for (int j = 0; j < 8; j++) acc[j] = 0.f;

    for (int i = 0; i < deg; i++) {
        int e = __ldg(&g_eid[beg + i]);     // uniform across warp -> broadcast
        int s = __ldg(&g_srcs[beg + i]);
        float4 a4 = al4[e];
        float al = (head == 0) ? a4.x : (head == 1) ? a4.y : (head == 2) ? a4.z : a4.w;
        const float4* p = (const float4*)(g_xl + (size_t)s * HID + lane * 8);
        float4 v0 = p[0], v1 = p[1];
        acc[0] += v0.x * al; acc[1] += v0.y * al; acc[2] += v0.z * al; acc[3] += v0.w * al;
        acc[4] += v1.x * al; acc[5] += v1.y * al; acc[6] += v1.z * al; acc[7] += v1.w * al;
    }

    int base = lane * 8;
    const float4* pb = (const float4*)(bias + base);
    float4 b0 = pb[0], b1 = pb[1];
    const float4* phv = (const float4*)(g_h + (size_t)warp * HID + base);
    float4 h0 = phv[0], h1 = phv[1];
    float v[8];
    v[0] = acc[0] + b0.x + h0.x; v[1] = acc[1] + b0.y + h0.y;
    v[2] = acc[2] + b0.z + h0.z; v[3] = acc[3] + b0.w + h0.w;
    v[4] = acc[4] + b1.x + h1.x; v[5] = acc[5] + b1.y + h1.y;
    v[6] = acc[6] + b1.z + h1.z; v[7] = acc[7] + b1.w + h1.w;
#pragma unroll
    for (int j = 0; j < 8; j++) v[j] = v[j] > 0.f ? v[j] : expm1f(v[j]);

    if (LAST == 0) {
        float4* po = (float4*)(g_h + (size_t)warp * HID + base);
        po[0] = make_float4(v[0], v[1], v[2], v[3]);
        po[1] = make_float4(v[4], v[5], v[6], v[7]);
    } else {
        const float4* pw = (const float4*)(clfW + base);
        float4 w0 = pw[0], w1 = pw[1];
        float s = v[0] * w0.x + v[1] * w0.y + v[2] * w0.z + v[3] * w0.w
                + v[4] * w1.x + v[5] * w1.y + v[6] * w1.z + v[7] * w1.w;
#pragma unroll
        for (int o = 16; o; o >>= 1) s += __shfl_xor_sync(0xffffffffu, s, o);
        if (lane == 0) preds[warp] = s + clfb[0];
    }
}

// ---------------- driver ----------------
extern "C" void kernel_launch(void* const* d_in, const int* in_sizes, int n_in,
                              void* d_out, int out_size)
{
    const float* x     = (const float*)d_in[0];
    const int*   ei    = (const int*)  d_in[1];
    const float* enc_W = (const float*)d_in[2];
    const float* enc_b = (const float*)d_in[3];
    const float* Wl0   = (const float*)d_in[4];
    const float* bl0   = (const float*)d_in[5];
    const float* Wr0   = (const float*)d_in[6];
    const float* br0   = (const float*)d_in[7];
    const float* att0  = (const float*)d_in[8];
    const float* bias0 = (const float*)d_in[9];
    const float* Wl1   = (const float*)d_in[10];
    const float* bl1   = (const float*)d_in[11];
    const float* Wr1   = (const float*)d_in[12];
    const float* br1   = (const float*)d_in[13];
    const float* att1  = (const float*)d_in[14];
    const float* bias1 = (const float*)d_in[15];
    const float* clf_W = (const float*)d_in[16];
    const float* clf_b = (const float*)d_in[17];

    float* out    = (float*)d_out;
    float* preds  = out;
    float* alpha0 = out + N_NODES;
    float* alpha1 = alpha0 + (size_t)E_TOT * NHEAD;

    float *ph, *pxl, *pxr;
    cudaGetSymbolAddress((void**)&ph,  g_h);
    cudaGetSymbolAddress((void**)&pxl, g_xl);
    cudaGetSymbolAddress((void**)&pxr, g_xr);
    __nv_bfloat16 *encT, *WT;
    cudaGetSymbolAddress((void**)&encT, g_encT);
    cudaGetSymbolAddress((void**)&WT,   g_WT);

    const int WSTRIDE = HID * HID * 3;
    const dim3 GG(2, (N_NODES + 127) / 128);

    // CSR build (reused by both layers)
    k_csr_zero<<<(N_NODES + 255) / 256, 256>>>();
    k_csr_count<<<(E_TOT + 255) / 256, 256>>>(ei);
    k_csr_scan<<<1, 1024>>>();
    k_csr_fill<<<(E_TOT + 255) / 256, 256>>>(ei);

    // prep: transpose + split weights into role-triplet layout
    k_wsplit<<<(HID * IN_DIM + 255) / 256, 256>>>(enc_W, IN_DIM, HID, encT);
    k_wsplit<<<(HID * HID + 255) / 256, 256>>>(Wl0, HID, HID, WT + 0 * WSTRIDE);
    k_wsplit<<<(HID * HID + 255) / 256, 256>>>(Wr0, HID, HID, WT + 1 * WSTRIDE);
    k_wsplit<<<(HID * HID + 255) / 256, 256>>>(Wl1, HID, HID, WT + 2 * WSTRIDE);
    k_wsplit<<<(HID * HID + 255) / 256, 256>>>(Wr1, HID, HID, WT + 3 * WSTRIDE);

    // encoder: h = x @ enc_W + enc_b
    gemm_tc<<<GG, 256>>>(x, encT, enc_b, ph, N_NODES, IN_DIM);

    for (int layer = 0; layer < 2; layer++) {
        const __nv_bfloat16* wl = WT + (layer * 2 + 0) * WSTRIDE;
        const __nv_bfloat16* wr = WT + (layer * 2 + 1) * WSTRIDE;
        const float* bl   = layer ? bl1 : bl0;
        const float* br   = layer ? br1 : br0;
        const float* att  = layer ? att1 : att0;
        const float* bias = layer ? bias1 : bias0;
        float* alphaOut   = layer ? alpha1 : alpha0;

        gemm_tc<<<GG, 256>>>(ph, wl, bl, pxl, N_NODES, HID);
        gemm_tc<<<GG, 256>>>(ph, wr, br, pxr, N_NODES, HID);
        k_edge_logits<<<(E_TOT + 7) / 8, 256>>>(ei, att);
        k_node_soft<<<(N_NODES + 7) / 8, 256>>>(alphaOut);
        if (layer == 0)
            k_node_agg<0><<<(N_NODES + 7) / 8, 256>>>(alphaOut, bias, nullptr, nullptr, nullptr);
        else
            k_node_agg<1><<<(N_NODES + 7) / 8, 256>>>(alphaOut, bias, clf_W, clf_b, preds);
    }
}

// round 8
// speedup vs baseline: 3.3144x; 1.1980x over previous
#include <cuda_runtime.h>
#include <cuda_bf16.h>
#include <math.h>
#include <stdint.h>
#include <string.h>

#define N_NODES 50000
#define E_EDGES 800000
#define E_TOT   850000   // E + N self loops
#define IN_DIM  1280
#define HID     256
#define NHEAD   4
#define DHEAD   64

// ---------------- scratch (device globals: no allocation allowed) ----------------
__device__ float g_h[N_NODES * HID];
__device__ float g_xl[N_NODES * HID];
__device__ float g_xr[N_NODES * HID];
__device__ float g_logits[E_TOT * NHEAD];     // only used for deg>SCAP fallback

// pre-split bf16 operands for tensor-core GEMMs
__device__ __nv_bfloat16 g_xhi[N_NODES * IN_DIM];
__device__ __nv_bfloat16 g_xlo[N_NODES * IN_DIM];
__device__ __nv_bfloat16 g_hhi[N_NODES * HID];
__device__ __nv_bfloat16 g_hlo[N_NODES * HID];

// CSR (in-edges per destination node), built once per launch
__device__ int g_cnt[N_NODES];
__device__ int g_off[N_NODES + 1];
__device__ int g_cur[N_NODES];
__device__ int g_eid[E_TOT];
__device__ int g_srcs[E_TOT];

// split weights, transposed to [N_out][3*K] bf16, role triplets per 8-k block:
// roles (B side): block 3b+0 = hi(k block b), 3b+1 = hi, 3b+2 = lo
__device__ __nv_bfloat16 g_encT[HID * IN_DIM * 3];
__device__ __nv_bfloat16 g_WT[4][HID * HID * 3];   // Wl0, Wr0, Wl1, Wr1

// ---------------- PTX helpers ----------------
__device__ __forceinline__ uint32_t smem_u32(const void* p) {
    uint32_t a;
    asm("{ .reg .u64 t; cvta.to.shared.u64 t, %1; cvt.u32.u64 %0, t; }" : "=r"(a) : "l"(p));
    return a;
}
__device__ __forceinline__ void ldsm_x4(uint32_t* r, uint32_t addr) {
    asm volatile("ldmatrix.sync.aligned.m8n8.x4.shared.b16 {%0,%1,%2,%3}, [%4];"
                 : "=r"(r[0]), "=r"(r[1]), "=r"(r[2]), "=r"(r[3]) : "r"(addr));
}
__device__ __forceinline__ void mma16816(float* c, const uint32_t* a, const uint32_t* b) {
    asm volatile("mma.sync.aligned.m16n8k16.row.col.f32.bf16.bf16.f32 "
                 "{%0,%1,%2,%3}, {%4,%5,%6,%7}, {%8,%9}, {%0,%1,%2,%3};"
                 : "+f"(c[0]), "+f"(c[1]), "+f"(c[2]), "+f"(c[3])
                 : "r"(a[0]), "r"(a[1]), "r"(a[2]), "r"(a[3]), "r"(b[0]), "r"(b[1]));
}

// ---------------- tensor-core GEMM: C[M,256] = A[M,K] @ B'[256,3K]^T + bias ----------
// A pre-split into Ahi/Alo bf16 [M][K]. Role triplets: A (hi, lo, hi) x B (hi, hi, lo).
// SOUT=1 additionally writes bf16 hi/lo split of C (for feeding the next GEMM).
template <int SOUT>
__global__ void __launch_bounds__(256, 2)
gemm_tc(const __nv_bfloat16* __restrict__ Ahi, const __nv_bfloat16* __restrict__ Alo,
        const __nv_bfloat16* __restrict__ B, const float* __restrict__ bias,
        float* __restrict__ C, __nv_bfloat16* __restrict__ Chi,
        __nv_bfloat16* __restrict__ Clo, int M, int K)
{
    const int K2 = 3 * K;
    const int nCh = K2 >> 5;
    __shared__ __align__(16) char smbuf[32768];

    const int tid  = threadIdx.x;
    const int lane = tid & 31;
    const int wid  = tid >> 5;
    const int mw   = wid & 1;
    const int nw   = wid >> 1;
    const int rowBase = blockIdx.y * 128;
    const int colBase = blockIdx.x * 128;

    float acc[4][4][4];
#pragma unroll
    for (int i = 0; i < 4; i++)
#pragma unroll
        for (int j = 0; j < 4; j++)
#pragma unroll
            for (int k = 0; k < 4; k++) acc[i][j][k] = 0.f;

    uint4 aReg[2], bReg[2];

    auto ldA = [&](int ch) {
#pragma unroll
        for (int i = 0; i < 2; i++) {
            int id = i * 256 + tid;
            int m = id >> 2, c = id & 3;
            int kb = ch * 4 + c;
            int b3 = kb / 3;
            int role = kb - 3 * b3;
            int rg = rowBase + m;
            const __nv_bfloat16* src = (role == 1) ? Alo : Ahi;
            if (rg < M) aReg[i] = *(const uint4*)(src + (size_t)rg * K + (b3 << 3));
            else        aReg[i] = make_uint4(0u, 0u, 0u, 0u);
        }
    };
    auto ldB = [&](int ch) {
#pragma unroll
        for (int i = 0; i < 2; i++) {
            int id = i * 256 + tid;
            int n = id >> 2, c = id & 3;
            bReg[i] = *(const uint4*)(B + (size_t)(colBase + n) * K2 + (ch << 5) + (c << 3));
        }
    };
    auto sts = [&](int buf) {
        char* sa = smbuf + buf * 16384;
        char* sb = sa + 8192;
#pragma unroll
        for (int i = 0; i < 2; i++) {
            int id = i * 256 + tid;
            int m = id >> 2, c = id & 3;
            uint32_t off = m * 64 + ((c ^ ((m >> 1) & 3)) << 4);
            *(uint4*)(sa + off) = aReg[i];
            *(uint4*)(sb + off) = bReg[i];
        }
    };

    ldA(0); ldB(0);
    for (int ch = 0; ch < nCh; ch++) {
        sts(ch & 1);
        __syncthreads();
        if (ch + 1 < nCh) { ldA(ch + 1); ldB(ch + 1); }

        uint32_t sA = smem_u32(smbuf + (ch & 1) * 16384);
        uint32_t sB = sA + 8192;
#pragma unroll
        for (int ks = 0; ks < 2; ks++) {
            uint32_t af[4][4], bf[2][4];
            int g = lane >> 3;
#pragma unroll
            for (int mt = 0; mt < 4; mt++) {
                int r = mw * 64 + mt * 16 + ((g & 1) << 3) + (lane & 7);
                int kb = ks * 2 + (g >> 1);
                ldsm_x4(af[mt], sA + r * 64 + ((kb ^ ((r >> 1) & 3)) << 4));
            }
#pragma unroll
            for (int p = 0; p < 2; p++) {
                int r = nw * 32 + p * 16 + (((g >> 1) & 1) << 3) + (lane & 7);
                int kb = ks * 2 + (g & 1);
                ldsm_x4(bf[p], sB + r * 64 + ((kb ^ ((r >> 1) & 3)) << 4));
            }
#pragma unroll
            for (int mt = 0; mt < 4; mt++)
#pragma unroll
                for (int nt = 0; nt < 4; nt++)
                    mma16816(acc[mt][nt], af[mt], &bf[nt >> 1][(nt & 1) * 2]);
        }
    }

#pragma unroll
    for (int mt = 0; mt < 4; mt++) {
        int m0 = rowBase + mw * 64 + mt * 16 + (lane >> 2);
#pragma unroll
        for (int half = 0; half < 2; half++) {
            int rg = m0 + half * 8;
            if (rg < M) {
                float* cp = C + (size_t)rg * 256;
#pragma unroll
                for (int nt = 0; nt < 4; nt++) {
                    int n0 = colBase + nw * 32 + nt * 8 + (lane & 3) * 2;
                    float2 o;
                    o.x = acc[mt][nt][half * 2 + 0] + bias[n0];
                    o.y = acc[mt][nt][half * 2 + 1] + bias[n0 + 1];
                    *(float2*)(cp + n0) = o;
                    if (SOUT) {
                        __nv_bfloat162 hb = __floats2bfloat162_rn(o.x, o.y);
                        float lx = o.x - __low2float(hb);
                        float ly = o.y - __high2float(hb);
                        __nv_bfloat162 lb = __floats2bfloat162_rn(lx, ly);
                        *(__nv_bfloat162*)(Chi + (size_t)rg * 256 + n0) = hb;
                        *(__nv_bfloat162*)(Clo + (size_t)rg * 256 + n0) = lb;
                    }
                }
            }
        }
    }
}

// ---------------- x split: fp32 -> hi/lo bf16 ----------------
__global__ void k_xsplit(const float* __restrict__ x,
                         __nv_bfloat16* __restrict__ hi, __nv_bfloat16* __restrict__ lo,
                         int n4)
{
    int idx = blockIdx.x * blockDim.x + threadIdx.x;
    if (idx >= n4) return;
    float4 v = ((const float4*)x)[idx];
    __nv_bfloat162 h0 = __floats2bfloat162_rn(v.x, v.y);
    __nv_bfloat162 h1 = __floats2bfloat162_rn(v.z, v.w);
    __nv_bfloat162 l0 = __floats2bfloat162_rn(v.x - __low2float(h0), v.y - __high2float(h0));
    __nv_bfloat162 l1 = __floats2bfloat162_rn(v.z - __low2float(h1), v.w - __high2float(h1));
    ((__nv_bfloat162*)hi)[idx * 2]     = h0;
    ((__nv_bfloat162*)hi)[idx * 2 + 1] = h1;
    ((__nv_bfloat162*)lo)[idx * 2]     = l0;
    ((__nv_bfloat162*)lo)[idx * 2 + 1] = l1;
}

// ---------------- weight transpose + split ----------------
__global__ void k_wsplit(const float* __restrict__ W, int K, int N,
                         __nv_bfloat16* __restrict__ out)
{
    int idx = blockIdx.x * blockDim.x + threadIdx.x;
    if (idx >= N * K) return;
    int n = idx / K, k = idx - n * K;
    float v = W[(size_t)k * N + n];
    __nv_bfloat16 h = __float2bfloat16(v);
    __nv_bfloat16 l = __float2bfloat16(v - __bfloat162float(h));
    int b = k >> 3, p = k & 7;
    size_t base = (size_t)n * 3 * K + (size_t)(3 * b) * 8 + p;
    out[base]      = h;
    out[base + 8]  = h;
    out[base + 16] = l;
}

// ---------------- CSR build ----------------
__global__ void k_csr_zero()
{
    int i = blockIdx.x * blockDim.x + threadIdx.x;
    if (i < N_NODES) g_cnt[i] = 0;
}
__global__ void k_csr_count(const int* __restrict__ ei)
{
    int e = blockIdx.x * blockDim.x + threadIdx.x;
    if (e >= E_TOT) return;
    int dst = (e < E_EDGES) ? ei[E_EDGES + e] : e - E_EDGES;
    atomicAdd(&g_cnt[dst], 1);
}
__global__ void __launch_bounds__(1024) k_csr_scan()
{
    __shared__ int sh[1024];
    int tid = threadIdx.x;
    int carry = 0;
    for (int base = 0; base < N_NODES; base += 1024) {
        int i = base + tid;
        int v = (i < N_NODES) ? g_cnt[i] : 0;
        int x = v;
#pragma unroll
        for (int o = 1; o < 1024; o <<= 1) {
            sh[tid] = x; __syncthreads();
            if (tid >= o) x += sh[tid - o];
            __syncthreads();
        }
        if (i < N_NODES) { g_off[i] = carry + x - v; g_cur[i] = carry + x - v; }
        sh[tid] = x; __syncthreads();
        carry += sh[1023];
        __syncthreads();
    }
    if (tid == 0) g_off[N_NODES] = carry;
}
__global__ void k_csr_fill(const int* __restrict__ ei)
{
    int e = blockIdx.x * blockDim.x + threadIdx.x;
    if (e >= E_TOT) return;
    int src, dst;
    if (e < E_EDGES) { src = ei[e]; dst = ei[E_EDGES + e]; }
    else             { src = e - E_EDGES; dst = src; }
    int pos = atomicAdd(&g_cur[dst], 1);
    g_eid[pos]  = e;
    g_srcs[pos] = src;
}

// ---------------- fused per-layer attention (warp per node) ----------------
// pass1: logits (xr in regs), pass2: softmax in smem, pass3: aggregate + epilogue
#define SCAP 128
template <int LAST>
__global__ void __launch_bounds__(256)
k_attn(const float* __restrict__ att, float* __restrict__ alphaOut,
       const float* __restrict__ bias, const float* __restrict__ clfW,
       const float* __restrict__ clfb, float* __restrict__ preds)
{
    __shared__ float4 sa[8][SCAP];
    int warp = (blockIdx.x * blockDim.x + threadIdx.x) >> 5;
    if (warp >= N_NODES) return;
    int lane = threadIdx.x & 31;
    int w = (threadIdx.x >> 5);
    int head = lane >> 3;
    int beg = g_off[warp];
    int deg = g_off[warp + 1] - beg;
    int base = lane * 8;
    float4* al4 = (float4*)alphaOut;
    float4* lg4 = (float4*)g_logits;
    const bool small = (deg <= SCAP);

    // node-resident operands
    const float4* pr = (const float4*)(g_xr + (size_t)warp * HID + base);
    float4 r0 = pr[0], r1 = pr[1];
    const float4* pa = (const float4*)(att + base);
    float4 a0 = pa[0], a1 = pa[1];

    // ---- pass 1: logits ----
    for (int i = 0; i < deg; i++) {
        int s = __ldg(&g_srcs[beg + i]);
        const float4* pl = (const float4*)(g_xl + (size_t)s * HID + base);
        float4 l0 = pl[0], l1 = pl[1];
        float sum, t;
        t = l0.x + r0.x; sum  = (t > 0.f ? t : 0.2f * t) * a0.x;
        t = l0.y + r0.y; sum += (t > 0.f ? t : 0.2f * t) * a0.y;
        t = l0.z + r0.z; sum += (t > 0.f ? t : 0.2f * t) * a0.z;
        t = l0.w + r0.w; sum += (t > 0.f ? t : 0.2f * t) * a0.w;
        t = l1.x + r1.x; sum += (t > 0.f ? t : 0.2f * t) * a1.x;
        t = l1.y + r1.y; sum += (t > 0.f ? t : 0.2f * t) * a1.y;
        t = l1.z + r1.z; sum += (t > 0.f ? t : 0.2f * t) * a1.z;
        t = l1.w + r1.w; sum += (t > 0.f ? t : 0.2f * t) * a1.w;
        sum += __shfl_xor_sync(0xffffffffu, sum, 4);
        sum += __shfl_xor_sync(0xffffffffu, sum, 2);
        sum += __shfl_xor_sync(0xffffffffu, sum, 1);
        if ((lane & 7) == 0) {
            if (small) ((float*)&sa[w][i])[head] = sum;
            else       g_logits[(size_t)(beg + i) * NHEAD + head] = sum;
        }
    }
    __syncwarp();

    // ---- pass 2: softmax ----
    float4 mx = make_float4(-INFINITY, -INFINITY, -INFINITY, -INFINITY);
    for (int i = lane; i < deg; i += 32) {
        float4 v = small ? sa[w][i] : lg4[beg + i];
        mx.x = fmaxf(mx.x, v.x); mx.y = fmaxf(mx.y, v.y);
        mx.z = fmaxf(mx.z, v.z); mx.w = fmaxf(mx.w, v.w);
    }
#pragma unroll
    for (int o = 16; o; o >>= 1) {
        mx.x = fmaxf(mx.x, __shfl_xor_sync(0xffffffffu, mx.x, o));
        mx.y = fmaxf(mx.y, __shfl_xor_sync(0xffffffffu, mx.y, o));
        mx.z = fmaxf(mx.z, __shfl_xor_sync(0xffffffffu, mx.z, o));
        mx.w = fmaxf(mx.w, __shfl_xor_sync(0xffffffffu, mx.w, o));
    }
    float4 sm = make_float4(0.f, 0.f, 0.f, 0.f);
    for (int i = lane; i < deg; i += 32) {
        float4 v = small ? sa[w][i] : lg4[beg + i];
        v.x = __expf(v.x - mx.x); v.y = __expf(v.y - mx.y);
        v.z = __expf(v.z - mx.z); v.w = __expf(v.w - mx.w);
        if (small) sa[w][i] = v; else lg4[beg + i] = v;
        sm.x += v.x; sm.y += v.y; sm.z += v.z; sm.w += v.w;
    }
#pragma unroll
    for (int o = 16; o; o >>= 1) {
        sm.x += __shfl_xor_sync(0xffffffffu, sm.x, o);
        sm.y += __shfl_xor_sync(0xffffffffu, sm.y, o);
        sm.z += __shfl_xor_sync(0xffffffffu, sm.z, o);
        sm.w += __shfl_xor_sync(0xffffffffu, sm.w, o);
    }
    float4 inv = make_float4(1.f / (sm.x + 1e-16f), 1.f / (sm.y + 1e-16f),
                             1.f / (sm.z + 1e-16f), 1.f / (sm.w + 1e-16f));
    __syncwarp();
    for (int i = lane; i < deg; i += 32) {
        float4 v = small ? sa[w][i] : lg4[beg + i];
        v.x *= inv.x; v.y *= inv.y; v.z *= inv.z; v.w *= inv.w;
        if (small) sa[w][i] = v; else lg4[beg + i] = v;
        al4[__ldg(&g_eid[beg + i])] = v;      // final alpha output
    }
    __syncwarp();

    // ---- pass 3: aggregate ----
    float acc[8];
#pragma unroll
    for (int j = 0; j < 8; j++) acc[j] = 0.f;
    for (int i = 0; i < deg; i++) {
        float al = small ? ((float*)&sa[w][i])[head]
                         : g_logits[(size_t)(beg + i) * NHEAD + head];
        int s = __ldg(&g_srcs[beg + i]);
        const float4* p = (const float4*)(g_xl + (size_t)s * HID + base);
        float4 v0 = p[0], v1 = p[1];
        acc[0] += v0.x * al; acc[1] += v0.y * al; acc[2] += v0.z * al; acc[3] += v0.w * al;
        acc[4] += v1.x * al; acc[5] += v1.y * al; acc[6] += v1.z * al; acc[7] += v1.w * al;
    }

    // ---- epilogue: bias + residual + ELU (+ h split or classifier) ----
    const float4* pb = (const float4*)(bias + base);
    float4 b0 = pb[0], b1 = pb[1];
    const float4* phv = (const float4*)(g_h + (size_t)warp * HID + base);
    float4 h0 = phv[0], h1 = phv[1];
    float v[8];
    v[0] = acc[0] + b0.x + h0.x; v[1] = acc[1] + b0.y + h0.y;
    v[2] = acc[2] + b0.z + h0.z; v[3] = acc[3] + b0.w + h0.w;
    v[4] = acc[4] + b1.x + h1.x; v[5] = acc[5] + b1.y + h1.y;
    v[6] = acc[6] + b1.z + h1.z; v[7] = acc[7] + b1.w + h1.w;
#pragma unroll
    for (int j = 0; j < 8; j++) v[j] = v[j] > 0.f ? v[j] : expm1f(v[j]);

    if (LAST == 0) {
        float4* po = (float4*)(g_h + (size_t)warp * HID + base);
        po[0] = make_float4(v[0], v[1], v[2], v[3]);
        po[1] = make_float4(v[4], v[5], v[6], v[7]);
        // bf16 hi/lo split for next layer's GEMMs
        uint32_t hw[4], lw[4];
#pragma unroll
        for (int j = 0; j < 4; j++) {
            __nv_bfloat162 hb = __floats2bfloat162_rn(v[2 * j], v[2 * j + 1]);
            float lx = v[2 * j] - __low2float(hb);
            float ly = v[2 * j + 1] - __high2float(hb);
            __nv_bfloat162 lb = __floats2bfloat162_rn(lx, ly);
            memcpy(&hw[j], &hb, 4); memcpy(&lw[j], &lb, 4);
        }
        *(uint4*)(g_hhi + (size_t)warp * HID + base) = make_uint4(hw[0], hw[1], hw[2], hw[3]);
        *(uint4*)(g_hlo + (size_t)warp * HID + base) = make_uint4(lw[0], lw[1], lw[2], lw[3]);
    } else {
        const float4* pw = (const float4*)(clfW + base);
        float4 w0 = pw[0], w1 = pw[1];
        float s = v[0] * w0.x + v[1] * w0.y + v[2] * w0.z + v[3] * w0.w
                + v[4] * w1.x + v[5] * w1.y + v[6] * w1.z + v[7] * w1.w;
#pragma unroll
        for (int o = 16; o; o >>= 1) s += __shfl_xor_sync(0xffffffffu, s, o);
        if (lane == 0) preds[warp] = s + clfb[0];
    }
}

// ---------------- driver ----------------
extern "C" void kernel_launch(void* const* d_in, const int* in_sizes, int n_in,
                              void* d_out, int out_size)
{
    const float* x     = (const float*)d_in[0];
    const int*   ei    = (const int*)  d_in[1];
    const float* enc_W = (const float*)d_in[2];
    const float* enc_b = (const float*)d_in[3];
    const float* Wl0   = (const float*)d_in[4];
    const float* bl0   = (const float*)d_in[5];
    const float* Wr0   = (const float*)d_in[6];
    const float* br0   = (const float*)d_in[7];
    const float* att0  = (const float*)d_in[8];
    const float* bias0 = (const float*)d_in[9];
    const float* Wl1   = (const float*)d_in[10];
    const float* bl1   = (const float*)d_in[11];
    const float* Wr1   = (const float*)d_in[12];
    const float* br1   = (const float*)d_in[13];
    const float* att1  = (const float*)d_in[14];
    const float* bias1 = (const float*)d_in[15];
    const float* clf_W = (const float*)d_in[16];
    const float* clf_b = (const float*)d_in[17];

    float* out    = (float*)d_out;
    float* preds  = out;
    float* alpha0 = out + N_NODES;
    float* alpha1 = alpha0 + (size_t)E_TOT * NHEAD;

    float *ph, *pxl, *pxr;
    cudaGetSymbolAddress((void**)&ph,  g_h);
    cudaGetSymbolAddress((void**)&pxl, g_xl);
    cudaGetSymbolAddress((void**)&pxr, g_xr);
    __nv_bfloat16 *encT, *WT, *xhi, *xlo, *hhi, *hlo;
    cudaGetSymbolAddress((void**)&encT, g_encT);
    cudaGetSymbolAddress((void**)&WT,   g_WT);
    cudaGetSymbolAddress((void**)&xhi,  g_xhi);
    cudaGetSymbolAddress((void**)&xlo,  g_xlo);
    cudaGetSymbolAddress((void**)&hhi,  g_hhi);
    cudaGetSymbolAddress((void**)&hlo,  g_hlo);

    const int WSTRIDE = HID * HID * 3;
    const dim3 GG(2, (N_NODES + 127) / 128);

    // launches 0..4 (prep), launch 5 = encoder GEMM (ncu -s 5 -c 1 captures it)
    k_xsplit<<<(N_NODES * IN_DIM / 4 + 255) / 256, 256>>>(x, xhi, xlo, N_NODES * IN_DIM / 4);
    k_wsplit<<<(HID * IN_DIM + 255) / 256, 256>>>(enc_W, IN_DIM, HID, encT);
    k_wsplit<<<(HID * HID + 255) / 256, 256>>>(Wl0, HID, HID, WT + 0 * WSTRIDE);
    k_wsplit<<<(HID * HID + 255) / 256, 256>>>(Wr0, HID, HID, WT + 1 * WSTRIDE);
    k_wsplit<<<(HID * HID + 255) / 256, 256>>>(Wl1, HID, HID, WT + 2 * WSTRIDE);

    // encoder: h = x @ enc_W + enc_b (fp32 + bf16-split outputs)
    gemm_tc<1><<<GG, 256>>>(xhi, xlo, encT, enc_b, ph, hhi, hlo, N_NODES, IN_DIM);

    k_wsplit<<<(HID * HID + 255) / 256, 256>>>(Wr1, HID, HID, WT + 3 * WSTRIDE);

    // CSR build (reused by both layers)
    k_csr_zero<<<(N_NODES + 255) / 256, 256>>>();
    k_csr_count<<<(E_TOT + 255) / 256, 256>>>(ei);
    k_csr_scan<<<1, 1024>>>();
    k_csr_fill<<<(E_TOT + 255) / 256, 256>>>(ei);

    for (int layer = 0; layer < 2; layer++) {
        const __nv_bfloat16* wl = WT + (layer * 2 + 0) * WSTRIDE;
        const __nv_bfloat16* wr = WT + (layer * 2 + 1) * WSTRIDE;
        const float* bl   = layer ? bl1 : bl0;
        const float* br   = layer ? br1 : br0;
        const float* att  = layer ? att1 : att0;
        const float* bias = layer ? bias1 : bias0;
        float* alphaOut   = layer ? alpha1 : alpha0;

        gemm_tc<0><<<GG, 256>>>(hhi, hlo, wl, bl, pxl, nullptr, nullptr, N_NODES, HID);
        gemm_tc<0><<<GG, 256>>>(hhi, hlo, wr, br, pxr, nullptr, nullptr, N_NODES, HID);
        if (layer == 0)
            k_attn<0><<<(N_NODES + 7) / 8, 256>>>(att, alphaOut, bias, nullptr, nullptr, nullptr);
        else
            k_attn<1><<<(N_NODES + 7) / 8, 256>>>(att, alphaOut, bias, clf_W, clf_b, preds);
    }
}